// round 15
// baseline (speedup 1.0000x reference)
#include <cuda_runtime.h>
#include <cuda_bf16.h>
#include <cstdint>

// VectorQuantizer — bf16 mma.sync screening (two-pass, 32 rows/warp) + lane-parallel
// exact fp32 rescoring that bit-replicates the reference numerics:
//   dist_k = fl( fl(||z||^2 + ||e_k||^2) - 2*C_k ), C_k = ascending-d fmaf chain from 0
//   argmin first-index tie-break; Zq = fl(z + fl(e-z)); loss = 1.25*mean((e-z)^2)
// R15: MMA asm is NON-volatile (pure register op) -> compiler may software-pipeline
// HMMAs across nt iterations. Everything else identical to R14.

typedef unsigned int u32;
typedef unsigned long long u64;

#define DDIM 64
#define KC 512
#define HW 4096
#define CHW 262144
#define NVEC 131072
#define THREADS 512
#define WARPS 16
#define GRID 148
#define TILE 512
#define TILEP 516                // padded zfp row stride -> conflict-free afr packing
#define NTILES (NVEC / TILE)     // 256
#define ZQ_ELEMS 8388608
#define LCAP 8                   // per-lane candidate slots

__device__ float g_blocksums[GRID];
__device__ unsigned int g_done = 0;

struct Smem {
    uint4 Bfrag[64 * 2 * 32];    // [nt][half][lane]: half h holds ks=2h,2h+1; 64KB
    float zfp[DDIM * TILEP];     // [d][vector] exact z (padded rows), 132096B
    float Bsh[KC];               // exact ||e_k||^2
    float An[TILE];              // exact ||z||^2
    u64   cbest[TILE];           // packed (S_bits<<32 | k), atomicMin
    u32   cand[THREADS * LCAP];  // per-lane candidate lists, 16KB
    float red[WARPS];
    float Bmax;
};
#define SMEM_TOTAL ((int)sizeof(Smem))   // ~218KB, 1 CTA/SM

__device__ __forceinline__ u32 packbf(float lo, float hi) {
    u32 r; asm("cvt.rn.bf16x2.f32 %0, %1, %2;" : "=r"(r) : "f"(hi), "f"(lo)); return r;
}
// NON-volatile: pure register function -> compiler may reorder/pipeline freely.
__device__ __forceinline__ void mma16816(float c[4], const u32 a[4], const u32 b0, const u32 b1) {
    asm("mma.sync.aligned.m16n8k16.row.col.f32.bf16.bf16.f32 "
        "{%0,%1,%2,%3}, {%4,%5,%6,%7}, {%8,%9}, {%0,%1,%2,%3};"
        : "+f"(c[0]), "+f"(c[1]), "+f"(c[2]), "+f"(c[3])
        : "r"(a[0]), "r"(a[1]), "r"(a[2]), "r"(a[3]), "r"(b0), "r"(b1));
}

// 8 approx scores for this warp's TWO m-tiles at n-tile nt.
// sc[2j+c]: row j in {rA,rB,rC,rD}, code k0+c. Identical in both passes.
__device__ __forceinline__ void score8(const Smem* sh, const u32 afr[2][4][4],
                                       int nt, int lane, int m4, float sc[8]) {
    uint4 q0 = sh->Bfrag[(nt * 2 + 0) * 32 + lane];   // ks0 (x,y), ks1 (z,w)
    uint4 q1 = sh->Bfrag[(nt * 2 + 1) * 32 + lane];   // ks2, ks3
    float c0a[4] = {0.f,0.f,0.f,0.f}, c0b[4] = {0.f,0.f,0.f,0.f};
    float c1a[4] = {0.f,0.f,0.f,0.f}, c1b[4] = {0.f,0.f,0.f,0.f};
    mma16816(c0a, afr[0][0], q0.x, q0.y);  mma16816(c1a, afr[1][0], q0.x, q0.y);
    mma16816(c0b, afr[0][2], q1.x, q1.y);  mma16816(c1b, afr[1][2], q1.x, q1.y);
    mma16816(c0a, afr[0][1], q0.z, q0.w);  mma16816(c1a, afr[1][1], q0.z, q0.w);
    mma16816(c0b, afr[0][3], q1.z, q1.w);  mma16816(c1b, afr[1][3], q1.z, q1.w);
    const int k0 = nt * 8 + 2 * m4;
    const float B0 = sh->Bsh[k0], B1 = sh->Bsh[k0 + 1];
    sc[0] = fmaf(-2.f, c0a[0] + c0b[0], B0);  sc[1] = fmaf(-2.f, c0a[1] + c0b[1], B1);
    sc[2] = fmaf(-2.f, c0a[2] + c0b[2], B0);  sc[3] = fmaf(-2.f, c0a[3] + c0b[3], B1);
    sc[4] = fmaf(-2.f, c1a[0] + c1b[0], B0);  sc[5] = fmaf(-2.f, c1a[1] + c1b[1], B1);
    sc[6] = fmaf(-2.f, c1a[2] + c1b[2], B0);  sc[7] = fmaf(-2.f, c1a[3] + c1b[3], B1);
}

// exact rescore (reference numerics; float4 loads, fmaf chain order unchanged)
// + deterministic lexicographic merge
__device__ __forceinline__ void exact_amin(Smem* sh, const float* __restrict__ E,
                                           int row, int k, float A) {
    const float4* er4 = (const float4*)(E + k * DDIM);
    float C = 0.f;
    #pragma unroll
    for (int i = 0; i < DDIM / 4; i++) {
        float4 e = __ldg(er4 + i);
        C = fmaf(sh->zfp[(4 * i + 0) * TILEP + row], e.x, C);
        C = fmaf(sh->zfp[(4 * i + 1) * TILEP + row], e.y, C);
        C = fmaf(sh->zfp[(4 * i + 2) * TILEP + row], e.z, C);
        C = fmaf(sh->zfp[(4 * i + 3) * TILEP + row], e.w, C);
    }
    float S = fmaf(-2.f, C, A + sh->Bsh[k]);
    u64 key = ((u64)__float_as_uint(S) << 32) | (u32)k;   // S>0 -> bits order-monotonic
    atomicMin(&sh->cbest[row], key);
}

__global__ void __launch_bounds__(THREADS, 1)
vq_mma_kernel(const float* __restrict__ inp, const float* __restrict__ E,
              float* __restrict__ out, int zq_off)
{
    extern __shared__ char smraw[];
    Smem* sh = (Smem*)smraw;

    const int tid = threadIdx.x;
    const int warp = tid >> 5;
    const int lane = tid & 31;
    const int m4 = lane & 3;
    const int qrow = lane >> 2;

    // ---- one-time staging: B fragments (bf16, uint4) + exact Bsh + Bmax ----
    for (int idx = tid; idx < 64 * 2 * 32; idx += THREADS) {
        int l = idx & 31, half = (idx >> 5) & 1, nt = idx >> 6;
        int kc = nt * 8 + (l >> 2);
        const float* er = E + kc * DDIM;
        int dA = (half * 2) * 16 + 2 * (l & 3);
        int dB = (half * 2 + 1) * 16 + 2 * (l & 3);
        uint4 v;
        v.x = packbf(er[dA],     er[dA + 1]);
        v.y = packbf(er[dA + 8], er[dA + 9]);
        v.z = packbf(er[dB],     er[dB + 1]);
        v.w = packbf(er[dB + 8], er[dB + 9]);
        sh->Bfrag[idx] = v;
    }
    {   // exact ||e||^2 (R2-verbatim), one code per thread (THREADS == KC)
        const int k = tid;
        const float* er = E + k * DDIM;
        float bsum = 0.f;
        #pragma unroll
        for (int d = 0; d < DDIM; d++) { float e = er[d]; bsum = bsum + e * e; }
        sh->Bsh[k] = bsum;
    }
    __syncthreads();
    if (tid == 0) {
        float m = 0.f;
        for (int k = 0; k < KC; k++) m = fmaxf(m, sh->Bsh[k]);
        sh->Bmax = m;
    }
    __syncthreads();
    const float Bmax = sh->Bmax;

    float ls = 0.f;

    for (int tile = blockIdx.x; tile < NTILES; tile += GRID) {
        const int base = tile * TILE;
        const int b = base >> 12, hw0 = base & 4095;
        const float* zsrc = inp + (size_t)b * CHW + hw0;

        __syncthreads();   // protect reused smem across tiles
        for (int i = tid; i < DDIM * TILE / 4; i += THREADS) {   // float4 z staging
            int d = i >> 7, v4 = (i & 127) * 4;
            float4 val = *(const float4*)(zsrc + (size_t)d * HW + v4);
            *(float4*)&sh->zfp[d * TILEP + v4] = val;
        }
        sh->cbest[tid] = 0xFFFFFFFFFFFFFFFFull;
        __syncthreads();
        {
            float A = 0.f;   // exact ||z||^2 ascending d (R2-verbatim)
            #pragma unroll
            for (int d = 0; d < DDIM; d++) { float a = sh->zfp[d * TILEP + tid]; A = A + a * a; }
            sh->An[tid] = A;
        }
        __syncthreads();

        // ---- A fragments: this warp's 32 vectors (TWO m-tiles) ----
        u32 afr[2][4][4];
        const int r0g = warp * 32 + qrow;
        #pragma unroll
        for (int m = 0; m < 2; m++) {
            const int rA = r0g + m * 16, rB = rA + 8;
            #pragma unroll
            for (int ks = 0; ks < 4; ks++) {
                const int d0 = ks * 16 + 2 * m4;    // bank = 8*m4 + qrow: conflict-free
                afr[m][ks][0] = packbf(sh->zfp[d0 * TILEP + rA],       sh->zfp[(d0 + 1) * TILEP + rA]);
                afr[m][ks][1] = packbf(sh->zfp[d0 * TILEP + rB],       sh->zfp[(d0 + 1) * TILEP + rB]);
                afr[m][ks][2] = packbf(sh->zfp[(d0 + 8) * TILEP + rA], sh->zfp[(d0 + 9) * TILEP + rA]);
                afr[m][ks][3] = packbf(sh->zfp[(d0 + 8) * TILEP + rB], sh->zfp[(d0 + 9) * TILEP + rB]);
            }
        }
        int rows[4]; float Arow[4];
        #pragma unroll
        for (int j = 0; j < 4; j++) {
            rows[j] = r0g + (j >> 1) * 16 + (j & 1) * 8;
            Arow[j] = sh->An[rows[j]];
        }

        // ---- pass 1: branchless running min ----
        float rm[4] = {3.402823466e38f, 3.402823466e38f, 3.402823466e38f, 3.402823466e38f};
        #pragma unroll 4
        for (int nt = 0; nt < 64; nt++) {
            float sc[8];
            score8(sh, afr, nt, lane, m4, sc);
            #pragma unroll
            for (int j = 0; j < 4; j++)
                rm[j] = fminf(rm[j], fminf(sc[2 * j], sc[2 * j + 1]));
        }
        float thr[4];
        #pragma unroll
        for (int j = 0; j < 4; j++) {
            float gm = rm[j];
            gm = fminf(gm, __shfl_xor_sync(0xffffffffu, gm, 1, 4));
            gm = fminf(gm, __shfl_xor_sync(0xffffffffu, gm, 2, 4));
            thr[j] = gm + (0.025f * sqrtf(Arow[j] * Bmax) + 5e-5f);
        }

        // ---- pass 2: recompute, collect hits into per-lane smem lists ----
        int myCnt = 0;
        const u32 cbase = tid * LCAP;
        #pragma unroll 4
        for (int nt = 0; nt < 64; nt++) {
            float sc[8];
            score8(sh, afr, nt, lane, m4, sc);
            const int k0 = nt * 8 + 2 * m4;
            #pragma unroll
            for (int j = 0; j < 4; j++) {
                if (sc[2 * j] <= thr[j]) {
                    if (myCnt < LCAP) sh->cand[cbase + myCnt] = ((u32)rows[j] << 16) | (u32)k0;
                    myCnt++;
                }
                if (sc[2 * j + 1] <= thr[j]) {
                    if (myCnt < LCAP) sh->cand[cbase + myCnt] = ((u32)rows[j] << 16) | (u32)(k0 + 1);
                    myCnt++;
                }
            }
        }

        const int ovf = (myCnt > LCAP);
        if (__any_sync(0xffffffffu, ovf)) {
            // fallback (P ~ 0): inline exact over every hit; min-merge is idempotent
            for (int nt = 0; nt < 64; nt++) {
                float sc[8];
                score8(sh, afr, nt, lane, m4, sc);
                const int k0 = nt * 8 + 2 * m4;
                #pragma unroll
                for (int j = 0; j < 4; j++) {
                    if (sc[2 * j]     <= thr[j]) exact_amin(sh, E, rows[j], k0,     Arow[j]);
                    if (sc[2 * j + 1] <= thr[j]) exact_amin(sh, E, rows[j], k0 + 1, Arow[j]);
                }
            }
        } else {
            // lane-parallel exact rescoring: each lane walks its own list
            int maxb = myCnt;
            #pragma unroll
            for (int off = 16; off; off >>= 1)
                maxb = max(maxb, __shfl_xor_sync(0xffffffffu, maxb, off));
            for (int i = 0; i < maxb; i++) {
                if (i < myCnt) {
                    u32 ent = sh->cand[cbase + i];
                    int row = ent >> 16, k = ent & 0xffff;
                    exact_amin(sh, E, row, k, sh->An[row]);
                }
            }
        }
        __syncthreads();

        // ---- emit: thread owns vector tid (64 d's), coalesced stores ----
        {
            const int v = tid;
            const int k = (int)(u32)(sh->cbest[v] & 0xffffffffu);
            const float4* er4 = (const float4*)(E + k * DDIM);
            float* o = out + zq_off + (size_t)b * CHW + hw0 + v;
            #pragma unroll
            for (int i = 0; i < DDIM / 4; i++) {
                float4 e = __ldg(er4 + i);
                float zv, t;
                zv = sh->zfp[(4 * i + 0) * TILEP + v];
                t = e.x - zv; ls += t * t; o[(size_t)(4 * i + 0) * HW] = zv + t;
                zv = sh->zfp[(4 * i + 1) * TILEP + v];
                t = e.y - zv; ls += t * t; o[(size_t)(4 * i + 1) * HW] = zv + t;
                zv = sh->zfp[(4 * i + 2) * TILEP + v];
                t = e.z - zv; ls += t * t; o[(size_t)(4 * i + 2) * HW] = zv + t;
                zv = sh->zfp[(4 * i + 3) * TILEP + v];
                t = e.w - zv; ls += t * t; o[(size_t)(4 * i + 3) * HW] = zv + t;
            }
        }
    }

    // ---- deterministic loss reduction + fused finalize ----
    #pragma unroll
    for (int off = 16; off; off >>= 1) ls += __shfl_down_sync(0xffffffffu, ls, off);
    if (lane == 0) sh->red[warp] = ls;
    __syncthreads();
    __shared__ unsigned int s_rank;
    if (tid == 0) {
        float t = 0.f;
        #pragma unroll
        for (int i = 0; i < WARPS; i++) t += sh->red[i];
        g_blocksums[blockIdx.x] = t;
        __threadfence();
        s_rank = atomicAdd(&g_done, 1u);
    }
    __syncthreads();
    if (s_rank == GRID - 1) {
        if (tid < 32) {
            double s = 0.0;
            for (int i = tid; i < GRID; i += 32) s += (double)g_blocksums[i];
            #pragma unroll
            for (int off = 16; off; off >>= 1) s += __shfl_down_sync(0xffffffffu, s, off);
            if (tid == 0) {
                if (zq_off >= 1) out[0] = (float)(s * (1.25 / 8388608.0));
                g_done = 0;   // reset for next graph replay
            }
        }
    }
}

extern "C" void kernel_launch(void* const* d_in, const int* in_sizes, int n_in,
                              void* d_out, int out_size)
{
    const float* inp = (const float*)d_in[0];  // [32,64,64,64] fp32
    const float* E   = (const float*)d_in[1];  // [512,64] fp32
    float* out = (float*)d_out;

    int zq_off = (out_size > ZQ_ELEMS) ? (out_size - ZQ_ELEMS) : 0;

    cudaFuncSetAttribute(vq_mma_kernel, cudaFuncAttributeMaxDynamicSharedMemorySize, SMEM_TOTAL);
    vq_mma_kernel<<<GRID, THREADS, SMEM_TOTAL>>>(inp, E, out, zq_off);
}

// round 16
// speedup vs baseline: 1.0026x; 1.0026x over previous
#include <cuda_runtime.h>
#include <cuda_bf16.h>
#include <cstdint>

// VectorQuantizer — bf16 mma.sync screening (two-pass, 32 rows/warp, software-pipelined
// B-fragment loads) + lane-parallel exact fp32 rescoring that bit-replicates the
// reference numerics:
//   dist_k = fl( fl(||z||^2 + ||e_k||^2) - 2*C_k ), C_k = ascending-d fmaf chain from 0
//   argmin first-index tie-break; Zq = fl(z + fl(e-z)); loss = 1.25*mean((e-z)^2)

typedef unsigned int u32;
typedef unsigned long long u64;

#define DDIM 64
#define KC 512
#define HW 4096
#define CHW 262144
#define NVEC 131072
#define THREADS 512
#define WARPS 16
#define GRID 148
#define TILE 512
#define TILEP 516                // padded zfp row stride -> conflict-free afr packing
#define NTILES (NVEC / TILE)     // 256
#define ZQ_ELEMS 8388608
#define LCAP 8                   // per-lane candidate slots

__device__ float g_blocksums[GRID];
__device__ unsigned int g_done = 0;

struct Smem {
    uint4 Bfrag[64 * 2 * 32];    // [nt][half][lane]: half h holds ks=2h,2h+1; 64KB
    float zfp[DDIM * TILEP];     // [d][vector] exact z (padded rows), 132096B
    float Bsh[KC];               // exact ||e_k||^2
    float An[TILE];              // exact ||z||^2
    u64   cbest[TILE];           // packed (S_bits<<32 | k), atomicMin
    u32   cand[THREADS * LCAP];  // per-lane candidate lists, 16KB
    float red[WARPS];
    float Bmax;
};
#define SMEM_TOTAL ((int)sizeof(Smem))   // ~218KB, 1 CTA/SM

__device__ __forceinline__ u32 packbf(float lo, float hi) {
    u32 r; asm("cvt.rn.bf16x2.f32 %0, %1, %2;" : "=r"(r) : "f"(hi), "f"(lo)); return r;
}
__device__ __forceinline__ void mma16816(float c[4], const u32 a[4], const u32 b0, const u32 b1) {
    asm("mma.sync.aligned.m16n8k16.row.col.f32.bf16.bf16.f32 "
        "{%0,%1,%2,%3}, {%4,%5,%6,%7}, {%8,%9}, {%0,%1,%2,%3};"
        : "+f"(c[0]), "+f"(c[1]), "+f"(c[2]), "+f"(c[3])
        : "r"(a[0]), "r"(a[1]), "r"(a[2]), "r"(a[3]), "r"(b0), "r"(b1));
}

// 8 approx scores from PRELOADED fragments q0,q1 (caller pipelines the LDS).
// Identical math in both passes -> identical score bits.
__device__ __forceinline__ void score8q(const float* __restrict__ Bsh,
                                        const u32 afr[2][4][4],
                                        uint4 q0, uint4 q1,
                                        int nt, int m4, float sc[8]) {
    float c0a[4] = {0.f,0.f,0.f,0.f}, c0b[4] = {0.f,0.f,0.f,0.f};
    float c1a[4] = {0.f,0.f,0.f,0.f}, c1b[4] = {0.f,0.f,0.f,0.f};
    mma16816(c0a, afr[0][0], q0.x, q0.y);  mma16816(c1a, afr[1][0], q0.x, q0.y);
    mma16816(c0b, afr[0][2], q1.x, q1.y);  mma16816(c1b, afr[1][2], q1.x, q1.y);
    mma16816(c0a, afr[0][1], q0.z, q0.w);  mma16816(c1a, afr[1][1], q0.z, q0.w);
    mma16816(c0b, afr[0][3], q1.z, q1.w);  mma16816(c1b, afr[1][3], q1.z, q1.w);
    const int k0 = nt * 8 + 2 * m4;
    const float B0 = Bsh[k0], B1 = Bsh[k0 + 1];
    sc[0] = fmaf(-2.f, c0a[0] + c0b[0], B0);  sc[1] = fmaf(-2.f, c0a[1] + c0b[1], B1);
    sc[2] = fmaf(-2.f, c0a[2] + c0b[2], B0);  sc[3] = fmaf(-2.f, c0a[3] + c0b[3], B1);
    sc[4] = fmaf(-2.f, c1a[0] + c1b[0], B0);  sc[5] = fmaf(-2.f, c1a[1] + c1b[1], B1);
    sc[6] = fmaf(-2.f, c1a[2] + c1b[2], B0);  sc[7] = fmaf(-2.f, c1a[3] + c1b[3], B1);
}

// exact rescore (reference numerics; float4 loads, fmaf chain order unchanged)
// + deterministic lexicographic merge
__device__ __forceinline__ void exact_amin(Smem* sh, const float* __restrict__ E,
                                           int row, int k, float A) {
    const float4* er4 = (const float4*)(E + k * DDIM);
    float C = 0.f;
    #pragma unroll
    for (int i = 0; i < DDIM / 4; i++) {
        float4 e = __ldg(er4 + i);
        C = fmaf(sh->zfp[(4 * i + 0) * TILEP + row], e.x, C);
        C = fmaf(sh->zfp[(4 * i + 1) * TILEP + row], e.y, C);
        C = fmaf(sh->zfp[(4 * i + 2) * TILEP + row], e.z, C);
        C = fmaf(sh->zfp[(4 * i + 3) * TILEP + row], e.w, C);
    }
    float S = fmaf(-2.f, C, A + sh->Bsh[k]);
    u64 key = ((u64)__float_as_uint(S) << 32) | (u32)k;   // S>0 -> bits order-monotonic
    atomicMin(&sh->cbest[row], key);
}

__global__ void __launch_bounds__(THREADS, 1)
vq_mma_kernel(const float* __restrict__ inp, const float* __restrict__ E,
              float* __restrict__ out, int zq_off)
{
    extern __shared__ char smraw[];
    Smem* sh = (Smem*)smraw;

    const int tid = threadIdx.x;
    const int warp = tid >> 5;
    const int lane = tid & 31;
    const int m4 = lane & 3;
    const int qrow = lane >> 2;

    // ---- one-time staging: B fragments (bf16, uint4) + exact Bsh + Bmax ----
    for (int idx = tid; idx < 64 * 2 * 32; idx += THREADS) {
        int l = idx & 31, half = (idx >> 5) & 1, nt = idx >> 6;
        int kc = nt * 8 + (l >> 2);
        const float* er = E + kc * DDIM;
        int dA = (half * 2) * 16 + 2 * (l & 3);
        int dB = (half * 2 + 1) * 16 + 2 * (l & 3);
        uint4 v;
        v.x = packbf(er[dA],     er[dA + 1]);
        v.y = packbf(er[dA + 8], er[dA + 9]);
        v.z = packbf(er[dB],     er[dB + 1]);
        v.w = packbf(er[dB + 8], er[dB + 9]);
        sh->Bfrag[idx] = v;
    }
    {   // exact ||e||^2 (R2-verbatim), one code per thread (THREADS == KC)
        const int k = tid;
        const float* er = E + k * DDIM;
        float bsum = 0.f;
        #pragma unroll
        for (int d = 0; d < DDIM; d++) { float e = er[d]; bsum = bsum + e * e; }
        sh->Bsh[k] = bsum;
    }
    __syncthreads();
    if (tid == 0) {
        float m = 0.f;
        for (int k = 0; k < KC; k++) m = fmaxf(m, sh->Bsh[k]);
        sh->Bmax = m;
    }
    __syncthreads();
    const float Bmax = sh->Bmax;

    float ls = 0.f;

    for (int tile = blockIdx.x; tile < NTILES; tile += GRID) {
        const int base = tile * TILE;
        const int b = base >> 12, hw0 = base & 4095;
        const float* zsrc = inp + (size_t)b * CHW + hw0;

        __syncthreads();   // protect reused smem across tiles
        for (int i = tid; i < DDIM * TILE / 4; i += THREADS) {   // float4 z staging
            int d = i >> 7, v4 = (i & 127) * 4;
            float4 val = *(const float4*)(zsrc + (size_t)d * HW + v4);
            *(float4*)&sh->zfp[d * TILEP + v4] = val;
        }
        sh->cbest[tid] = 0xFFFFFFFFFFFFFFFFull;
        __syncthreads();
        {
            float A = 0.f;   // exact ||z||^2 ascending d (R2-verbatim)
            #pragma unroll
            for (int d = 0; d < DDIM; d++) { float a = sh->zfp[d * TILEP + tid]; A = A + a * a; }
            sh->An[tid] = A;
        }
        __syncthreads();

        // ---- A fragments: this warp's 32 vectors (TWO m-tiles) ----
        u32 afr[2][4][4];
        const int r0g = warp * 32 + qrow;
        #pragma unroll
        for (int m = 0; m < 2; m++) {
            const int rA = r0g + m * 16, rB = rA + 8;
            #pragma unroll
            for (int ks = 0; ks < 4; ks++) {
                const int d0 = ks * 16 + 2 * m4;    // bank = 8*m4 + qrow: conflict-free
                afr[m][ks][0] = packbf(sh->zfp[d0 * TILEP + rA],       sh->zfp[(d0 + 1) * TILEP + rA]);
                afr[m][ks][1] = packbf(sh->zfp[d0 * TILEP + rB],       sh->zfp[(d0 + 1) * TILEP + rB]);
                afr[m][ks][2] = packbf(sh->zfp[(d0 + 8) * TILEP + rA], sh->zfp[(d0 + 9) * TILEP + rA]);
                afr[m][ks][3] = packbf(sh->zfp[(d0 + 8) * TILEP + rB], sh->zfp[(d0 + 9) * TILEP + rB]);
            }
        }
        int rows[4]; float Arow[4];
        #pragma unroll
        for (int j = 0; j < 4; j++) {
            rows[j] = r0g + (j >> 1) * 16 + (j & 1) * 8;
            Arow[j] = sh->An[rows[j]];
        }

        // ---- pass 1: branchless running min, pipelined Bfrag loads ----
        float rm[4] = {3.402823466e38f, 3.402823466e38f, 3.402823466e38f, 3.402823466e38f};
        {
            uint4 q0 = sh->Bfrag[lane];
            uint4 q1 = sh->Bfrag[32 + lane];
            #pragma unroll 4
            for (int nt = 0; nt < 64; nt++) {
                const int nn = (nt + 1) & 63;              // branchless wrap
                uint4 p0 = sh->Bfrag[(nn * 2 + 0) * 32 + lane];
                uint4 p1 = sh->Bfrag[(nn * 2 + 1) * 32 + lane];
                float sc[8];
                score8q(sh->Bsh, afr, q0, q1, nt, m4, sc);
                #pragma unroll
                for (int j = 0; j < 4; j++)
                    rm[j] = fminf(rm[j], fminf(sc[2 * j], sc[2 * j + 1]));
                q0 = p0; q1 = p1;
            }
        }
        float thr[4];
        #pragma unroll
        for (int j = 0; j < 4; j++) {
            float gm = rm[j];
            gm = fminf(gm, __shfl_xor_sync(0xffffffffu, gm, 1, 4));
            gm = fminf(gm, __shfl_xor_sync(0xffffffffu, gm, 2, 4));
            thr[j] = gm + (0.025f * sqrtf(Arow[j] * Bmax) + 5e-5f);
        }

        // ---- pass 2: recompute (pipelined), collect hits into per-lane lists ----
        int myCnt = 0;
        const u32 cbase = tid * LCAP;
        {
            uint4 q0 = sh->Bfrag[lane];
            uint4 q1 = sh->Bfrag[32 + lane];
            #pragma unroll 4
            for (int nt = 0; nt < 64; nt++) {
                const int nn = (nt + 1) & 63;
                uint4 p0 = sh->Bfrag[(nn * 2 + 0) * 32 + lane];
                uint4 p1 = sh->Bfrag[(nn * 2 + 1) * 32 + lane];
                float sc[8];
                score8q(sh->Bsh, afr, q0, q1, nt, m4, sc);
                const int k0 = nt * 8 + 2 * m4;
                #pragma unroll
                for (int j = 0; j < 4; j++) {
                    if (sc[2 * j] <= thr[j]) {
                        if (myCnt < LCAP) sh->cand[cbase + myCnt] = ((u32)rows[j] << 16) | (u32)k0;
                        myCnt++;
                    }
                    if (sc[2 * j + 1] <= thr[j]) {
                        if (myCnt < LCAP) sh->cand[cbase + myCnt] = ((u32)rows[j] << 16) | (u32)(k0 + 1);
                        myCnt++;
                    }
                }
                q0 = p0; q1 = p1;
            }
        }

        const int ovf = (myCnt > LCAP);
        if (__any_sync(0xffffffffu, ovf)) {
            // fallback (P ~ 0): inline exact over every hit; min-merge is idempotent
            for (int nt = 0; nt < 64; nt++) {
                uint4 q0 = sh->Bfrag[(nt * 2 + 0) * 32 + lane];
                uint4 q1 = sh->Bfrag[(nt * 2 + 1) * 32 + lane];
                float sc[8];
                score8q(sh->Bsh, afr, q0, q1, nt, m4, sc);
                const int k0 = nt * 8 + 2 * m4;
                #pragma unroll
                for (int j = 0; j < 4; j++) {
                    if (sc[2 * j]     <= thr[j]) exact_amin(sh, E, rows[j], k0,     Arow[j]);
                    if (sc[2 * j + 1] <= thr[j]) exact_amin(sh, E, rows[j], k0 + 1, Arow[j]);
                }
            }
        } else {
            // lane-parallel exact rescoring: each lane walks its own list
            int maxb = myCnt;
            #pragma unroll
            for (int off = 16; off; off >>= 1)
                maxb = max(maxb, __shfl_xor_sync(0xffffffffu, maxb, off));
            for (int i = 0; i < maxb; i++) {
                if (i < myCnt) {
                    u32 ent = sh->cand[cbase + i];
                    int row = ent >> 16, k = ent & 0xffff;
                    exact_amin(sh, E, row, k, sh->An[row]);
                }
            }
        }
        __syncthreads();

        // ---- emit: thread owns vector tid (64 d's), coalesced stores ----
        {
            const int v = tid;
            const int k = (int)(u32)(sh->cbest[v] & 0xffffffffu);
            const float4* er4 = (const float4*)(E + k * DDIM);
            float* o = out + zq_off + (size_t)b * CHW + hw0 + v;
            #pragma unroll
            for (int i = 0; i < DDIM / 4; i++) {
                float4 e = __ldg(er4 + i);
                float zv, t;
                zv = sh->zfp[(4 * i + 0) * TILEP + v];
                t = e.x - zv; ls += t * t; o[(size_t)(4 * i + 0) * HW] = zv + t;
                zv = sh->zfp[(4 * i + 1) * TILEP + v];
                t = e.y - zv; ls += t * t; o[(size_t)(4 * i + 1) * HW] = zv + t;
                zv = sh->zfp[(4 * i + 2) * TILEP + v];
                t = e.z - zv; ls += t * t; o[(size_t)(4 * i + 2) * HW] = zv + t;
                zv = sh->zfp[(4 * i + 3) * TILEP + v];
                t = e.w - zv; ls += t * t; o[(size_t)(4 * i + 3) * HW] = zv + t;
            }
        }
    }

    // ---- deterministic loss reduction + fused finalize ----
    #pragma unroll
    for (int off = 16; off; off >>= 1) ls += __shfl_down_sync(0xffffffffu, ls, off);
    if (lane == 0) sh->red[warp] = ls;
    __syncthreads();
    __shared__ unsigned int s_rank;
    if (tid == 0) {
        float t = 0.f;
        #pragma unroll
        for (int i = 0; i < WARPS; i++) t += sh->red[i];
        g_blocksums[blockIdx.x] = t;
        __threadfence();
        s_rank = atomicAdd(&g_done, 1u);
    }
    __syncthreads();
    if (s_rank == GRID - 1) {
        if (tid < 32) {
            double s = 0.0;
            for (int i = tid; i < GRID; i += 32) s += (double)g_blocksums[i];
            #pragma unroll
            for (int off = 16; off; off >>= 1) s += __shfl_down_sync(0xffffffffu, s, off);
            if (tid == 0) {
                if (zq_off >= 1) out[0] = (float)(s * (1.25 / 8388608.0));
                g_done = 0;   // reset for next graph replay
            }
        }
    }
}

extern "C" void kernel_launch(void* const* d_in, const int* in_sizes, int n_in,
                              void* d_out, int out_size)
{
    const float* inp = (const float*)d_in[0];  // [32,64,64,64] fp32
    const float* E   = (const float*)d_in[1];  // [512,64] fp32
    float* out = (float*)d_out;

    int zq_off = (out_size > ZQ_ELEMS) ? (out_size - ZQ_ELEMS) : 0;

    cudaFuncSetAttribute(vq_mma_kernel, cudaFuncAttributeMaxDynamicSharedMemorySize, SMEM_TOTAL);
    vq_mma_kernel<<<GRID, THREADS, SMEM_TOTAL>>>(inp, E, out, zq_off);
}